// round 3
// baseline (speedup 1.0000x reference)
#include <cuda_runtime.h>
#include <math.h>

// Problem constants
#define BB   64
#define SS   1024
#define DD   1024
#define EE   8
#define KK   2

#define TPB  256            // tokens per block in main kernel (also threads/block)
#define CH   32             // d-chunk per staging step
#define ROWP 36             // padded row length in floats (32 data + 4 pad) -> conflict-free
#define NBLK2 (BB*SS/TPB)   // 256 blocks

#define OFF_IDX  (BB*SS*EE)          // 524288
#define OFF_LOSS (OFF_IDX + BB*KK)   // 524416

// ---------------- scratch (no allocations allowed) ----------------
__device__ float g_M[DD*EE];            // folded weight: M[d][e]
__device__ float g_c[EE];               // folded bias:   c[e] = bq . key_emb[e]
__device__ float g_part_scores[NBLK2*EE];
__device__ float g_part_aux[NBLK2];
__device__ float g_mask2d[BB*EE];

// ---------------- packed f32x2 helpers (Blackwell FFMA2) ----------------
#define PACKF2(dst, lo, hi) asm("mov.b64 %0, {%1, %2};" : "=l"(dst) : "f"(lo), "f"(hi))
#define UNPACKF2(lo, hi, src) asm("mov.b64 {%0, %1}, %2;" : "=f"(lo), "=f"(hi) : "l"(src))
#define FFMA2(acc, a, b) asm("fma.rn.f32x2 %0, %1, %2, %0;" : "+l"(acc) : "l"(a), "l"(b))

// ============================================================
// Kernel 1: fold M[d][e] = sum_o Wq[o][d] * key_emb[e][o]
//           and c[e] = sum_o bq[o] * key_emb[e][o]
// grid = 5 blocks x 256 threads. Blocks 0..3 compute M, block 4 computes c.
// ============================================================
__global__ void k1_prep(const float* __restrict__ Wq,
                        const float* __restrict__ bq,
                        const float* __restrict__ key) {
    __shared__ float kes[DD*EE];   // key transposed: kes[o*8+e], 32 KB
    int tid = threadIdx.x;
    if (blockIdx.x < 4) {
        for (int i = tid; i < DD*EE; i += 256) {
            int e = i / DD, o = i % DD;
            kes[o*EE + e] = key[i];
        }
        __syncthreads();
        int d = blockIdx.x * 256 + tid;
        float acc[EE];
        #pragma unroll
        for (int e = 0; e < EE; e++) acc[e] = 0.f;
        for (int o = 0; o < DD; o++) {
            float w = Wq[(size_t)o*DD + d];          // coalesced across threads
            const float4* kr = (const float4*)&kes[o*EE];
            float4 k0 = kr[0], k1 = kr[1];
            acc[0] = fmaf(w, k0.x, acc[0]);
            acc[1] = fmaf(w, k0.y, acc[1]);
            acc[2] = fmaf(w, k0.z, acc[2]);
            acc[3] = fmaf(w, k0.w, acc[3]);
            acc[4] = fmaf(w, k1.x, acc[4]);
            acc[5] = fmaf(w, k1.y, acc[5]);
            acc[6] = fmaf(w, k1.z, acc[6]);
            acc[7] = fmaf(w, k1.w, acc[7]);
        }
        #pragma unroll
        for (int e = 0; e < EE; e++) g_M[d*EE + e] = acc[e];
    } else {
        // c[e]: one warp per expert
        int w = tid >> 5, l = tid & 31;
        float s = 0.f;
        for (int o = l; o < DD; o += 32) s = fmaf(bq[o], key[w*DD + o], s);
        #pragma unroll
        for (int off = 16; off; off >>= 1) s += __shfl_down_sync(0xffffffffu, s, off);
        if (l == 0) g_c[w] = s;
    }
}

// ============================================================
// Kernel 2: per-token logits -> softmax -> per-block partial
//           score sums [E] and aux-loss partial. One thread = one token.
//           x staged through shared in CH-wide chunks (coalesced);
//           M broadcast from shared (uniform addresses).
// dyn smem = M (32 KB) + x tile (256*36*4 = 36 KB) = 69632 B
// ============================================================
__global__ void __launch_bounds__(TPB) k2_main(const float* __restrict__ x) {
    extern __shared__ float smem2[];
    float* Msh = smem2;                // DD*EE floats
    float* xt  = smem2 + DD*EE;        // TPB*ROWP floats
    const int tid  = threadIdx.x;
    const int tok0 = blockIdx.x * TPB;

    for (int i = tid; i < DD*EE; i += TPB) Msh[i] = g_M[i];

    unsigned long long acc0 = 0ull, acc1 = 0ull, acc2 = 0ull, acc3 = 0ull; // (+0,+0) pairs
    const ulonglong2* M128 = (const ulonglong2*)Msh;   // M128[d*2 + {0,1}] = one 8-float row

    for (int c = 0; c < DD/CH; c++) {
        const int d0 = c * CH;
        __syncthreads();   // previous chunk's compute done before overwriting tile
        #pragma unroll
        for (int i = 0; i < CH/4; i++) {               // 8 float4 per thread
            int idx = i*TPB + tid;
            int r = idx >> 3;                           // 8 float4 per row
            int j4 = idx & 7;
            float4 v = *(const float4*)(x + (size_t)(tok0 + r)*DD + d0 + j4*4);
            *(float4*)(xt + r*ROWP + j4*4) = v;
        }
        __syncthreads();
        const float* row = xt + tid*ROWP;
        #pragma unroll
        for (int j4 = 0; j4 < CH/4; j4++) {
            float4 xv = *(const float4*)(row + j4*4);
            int d = d0 + j4*4;
            unsigned long long xp;
            ulonglong2 p0, p1;
            // d+0
            PACKF2(xp, xv.x, xv.x);
            p0 = M128[(d+0)*2]; p1 = M128[(d+0)*2+1];
            FFMA2(acc0, xp, p0.x); FFMA2(acc1, xp, p0.y);
            FFMA2(acc2, xp, p1.x); FFMA2(acc3, xp, p1.y);
            // d+1
            PACKF2(xp, xv.y, xv.y);
            p0 = M128[(d+1)*2]; p1 = M128[(d+1)*2+1];
            FFMA2(acc0, xp, p0.x); FFMA2(acc1, xp, p0.y);
            FFMA2(acc2, xp, p1.x); FFMA2(acc3, xp, p1.y);
            // d+2
            PACKF2(xp, xv.z, xv.z);
            p0 = M128[(d+2)*2]; p1 = M128[(d+2)*2+1];
            FFMA2(acc0, xp, p0.x); FFMA2(acc1, xp, p0.y);
            FFMA2(acc2, xp, p1.x); FFMA2(acc3, xp, p1.y);
            // d+3
            PACKF2(xp, xv.w, xv.w);
            p0 = M128[(d+3)*2]; p1 = M128[(d+3)*2+1];
            FFMA2(acc0, xp, p0.x); FFMA2(acc1, xp, p0.y);
            FFMA2(acc2, xp, p1.x); FFMA2(acc3, xp, p1.y);
        }
    }

    float a[EE];
    UNPACKF2(a[0], a[1], acc0);
    UNPACKF2(a[2], a[3], acc1);
    UNPACKF2(a[4], a[5], acc2);
    UNPACKF2(a[6], a[7], acc3);

    const float scale = 0.03125f;   // 1024^-0.5
    float l[EE];
    #pragma unroll
    for (int e = 0; e < EE; e++) l[e] = (a[e] + g_c[e]) * scale;

    // softmax over E=8
    float m = l[0];
    #pragma unroll
    for (int e = 1; e < EE; e++) m = fmaxf(m, l[e]);
    float w[EE];
    float sum = 0.f;
    #pragma unroll
    for (int e = 0; e < EE; e++) { w[e] = expf(l[e] - m); sum += w[e]; }
    float inv = 1.f / sum;
    float aux = 0.f;
    #pragma unroll
    for (int e = 0; e < EE; e++) {
        w[e] *= inv;
        aux += w[e] * logf(w[e] + 1e-9f);
    }

    // deterministic block reduction: warp shfl then warp-leader table
    #pragma unroll
    for (int e = 0; e < EE; e++) {
        #pragma unroll
        for (int off = 16; off; off >>= 1) w[e] += __shfl_down_sync(0xffffffffu, w[e], off);
    }
    #pragma unroll
    for (int off = 16; off; off >>= 1) aux += __shfl_down_sync(0xffffffffu, aux, off);

    __shared__ float rs[8][9];
    __shared__ float ra[8];
    int wid = tid >> 5, lid = tid & 31;
    if (lid == 0) {
        #pragma unroll
        for (int e = 0; e < EE; e++) rs[wid][e] = w[e];
        ra[wid] = aux;
    }
    __syncthreads();
    if (tid < EE) {
        float s = 0.f;
        #pragma unroll
        for (int k = 0; k < 8; k++) s += rs[k][tid];
        g_part_scores[blockIdx.x*EE + tid] = s;
    }
    if (tid == EE) {
        float s = 0.f;
        #pragma unroll
        for (int k = 0; k < 8; k++) s += ra[k];
        g_part_aux[blockIdx.x] = s;
    }
}

// ============================================================
// Kernel 3: finalize. scores per batch, top-2 (jax tie rule: strict >
// keeps lowest index), mask2d, usage counts -> KL, aux mean -> loss.
// Writes indices (as float) and loss to d_out.
// ============================================================
__global__ void k3_finalize(float* __restrict__ out) {
    __shared__ float sc[64][EE];
    __shared__ int cnt[EE];
    __shared__ float ax[256];
    int tid = threadIdx.x;
    if (tid < EE) cnt[tid] = 0;
    ax[tid] = g_part_aux[tid];
    if (tid < BB) {
        #pragma unroll
        for (int e = 0; e < EE; e++) {
            float s = 0.f;
            #pragma unroll
            for (int c = 0; c < 4; c++) s += g_part_scores[(tid*4 + c)*EE + e];
            sc[tid][e] = s;   // proportional to mean; top-k invariant
        }
    }
    __syncthreads();
    if (tid < BB) {
        int i0 = 0; float v0 = sc[tid][0];
        #pragma unroll
        for (int e = 1; e < EE; e++) if (sc[tid][e] > v0) { v0 = sc[tid][e]; i0 = e; }
        int i1 = -1; float v1 = -3.402823466e38f;
        #pragma unroll
        for (int e = 0; e < EE; e++) if (e != i0 && sc[tid][e] > v1) { v1 = sc[tid][e]; i1 = e; }
        out[OFF_IDX + tid*KK + 0] = (float)i0;
        out[OFF_IDX + tid*KK + 1] = (float)i1;
        #pragma unroll
        for (int e = 0; e < EE; e++)
            g_mask2d[tid*EE + e] = (e == i0 || e == i1) ? 1.f : 0.f;
        atomicAdd(&cnt[i0], 1);
        atomicAdd(&cnt[i1], 1);
    }
    __syncthreads();
    // deterministic tree reduce of aux partials
    for (int s = 128; s > 0; s >>= 1) {
        if (tid < s) ax[tid] += ax[tid + s];
        __syncthreads();
    }
    if (tid == 0) {
        float aux_mean = ax[0] / (float)(BB*SS*EE);
        const float ideal = 1.0f / (float)EE;
        float kl = 0.f;
        #pragma unroll
        for (int e = 0; e < EE; e++) {
            float up = (float)cnt[e] / (float)BB;   // == mask2d.sum(0) * S/(B*S)
            kl += ideal * (logf(ideal) - logf(up));
        }
        kl /= (float)EE;
        out[OFF_LOSS] = 1e-3f * kl + 1e-3f * aux_mean;
    }
}

// ============================================================
// Kernel 4: broadcast mask2d -> mask[B,S,E] in d_out (STG.128 x2/token)
// ============================================================
__global__ void k4_mask(float* __restrict__ out) {
    int t = blockIdx.x * blockDim.x + threadIdx.x;   // token id
    if (t >= BB*SS) return;
    int b = t >> 10;
    const float4* mm = (const float4*)&g_mask2d[b*EE];
    float4 m0 = mm[0], m1 = mm[1];
    float4* o = (float4*)(out + (size_t)t*EE);
    o[0] = m0; o[1] = m1;
}

// ============================================================
extern "C" void kernel_launch(void* const* d_in, const int* in_sizes, int n_in,
                              void* d_out, int out_size) {
    const float* x   = (const float*)d_in[0];
    const float* Wq  = (const float*)d_in[1];
    const float* bq  = (const float*)d_in[2];
    const float* key = (const float*)d_in[3];
    float* out = (float*)d_out;

    k1_prep<<<5, 256>>>(Wq, bq, key);

    size_t sm2 = (size_t)(DD*EE + TPB*ROWP) * sizeof(float);  // 69632 B
    cudaFuncSetAttribute(k2_main, cudaFuncAttributeMaxDynamicSharedMemorySize, (int)sm2);
    k2_main<<<NBLK2, TPB, sm2>>>(x);

    k3_finalize<<<1, 256>>>(out);
    k4_mask<<<(BB*SS + 255)/256, 256>>>(out);
}

// round 6
// speedup vs baseline: 4.1519x; 4.1519x over previous
#include <cuda_runtime.h>
#include <cstdint>
#include <math.h>

// Problem constants
#define BB   64
#define SS   1024
#define DD   1024
#define EE   8
#define KK   2

// k2 config
#define THR2  128             // threads per block
#define TOKB  256             // tokens per block (2 per thread: tid, tid+128)
#define NBLK2 (BB*SS/TOKB)    // 256 blocks
#define CH    32              // d-chunk per pipeline stage
#define NCH   (DD/CH)         // 32 stages
#define ROWP  36              // padded row (floats): lane-stride 144B -> conflict-free LDS.128
#define TILE_F (TOKB*ROWP)    // 9216 floats per tile buffer

// k1 config
#define OCHUNK 16
#define NOC    64             // o-chunks (2 halves x 32)

#define OFF_IDX  (BB*SS*EE)          // 524288
#define OFF_LOSS (OFF_IDX + BB*KK)   // 524416

// ---------------- scratch (no allocations allowed) ----------------
__device__ __align__(16) float g_Mpart[NOC*DD*EE];   // 2 MB split-K partials
__device__ __align__(16) float g_M[DD*EE];           // folded weight M[d][e]
__device__ __align__(16) float g_c[EE];              // folded bias c[e]
__device__ __align__(16) float g_part_scores[NBLK2*EE];
__device__ __align__(16) float g_part_aux[NBLK2];
__device__ __align__(16) float g_mask2d[BB*EE];

// ---------------- packed f32x2 helpers (Blackwell FFMA2) ----------------
#define PACKF2(dst, lo, hi) asm("mov.b64 %0, {%1, %2};" : "=l"(dst) : "f"(lo), "f"(hi))
#define UNPACKF2(lo, hi, src) asm("mov.b64 {%0, %1}, %2;" : "=f"(lo), "=f"(hi) : "l"(src))
#define FFMA2(acc, a, b) asm("fma.rn.f32x2 %0, %1, %2, %0;" : "+l"(acc) : "l"(a), "l"(b))

__device__ __forceinline__ void cpa16(unsigned int sdst, const float* gsrc) {
    asm volatile("cp.async.cg.shared.global [%0], [%1], 16;\n" :: "r"(sdst), "l"(gsrc));
}

// ============================================================
// Kernel 1a (x2 halves): split-K partials of M[d][e] = sum_o Wq[o][d]*key[e][o]
// grid = 128 blocks x 256 thr. block -> (o-chunk of 16, d-quarter of 256).
// ============================================================
__global__ void k1a(const float* __restrict__ Wq, const float* __restrict__ key, int half) {
    __shared__ float ks[OCHUNK][EE];
    const int tid = threadIdx.x;
    const int oc = half*32 + (blockIdx.x >> 2);
    const int q  = blockIdx.x & 3;
    if (tid < OCHUNK*EE) {
        int ol = tid >> 3, e = tid & 7;
        ks[ol][e] = key[e*DD + oc*OCHUNK + ol];
    }
    __syncthreads();
    const int d = q*256 + tid;
    const int o0 = oc*OCHUNK;
    float acc[EE];
    #pragma unroll
    for (int e = 0; e < EE; e++) acc[e] = 0.f;
    #pragma unroll
    for (int j = 0; j < OCHUNK; j++) {
        float w = Wq[(size_t)(o0 + j)*DD + d];     // coalesced, MLP=16
        #pragma unroll
        for (int e = 0; e < EE; e++) acc[e] = fmaf(w, ks[j][e], acc[e]);
    }
    float4* dst = (float4*)&g_Mpart[(size_t)oc*DD*EE + (size_t)d*EE];
    dst[0] = make_float4(acc[0], acc[1], acc[2], acc[3]);
    dst[1] = make_float4(acc[4], acc[5], acc[6], acc[7]);
}

// Kernel 1b: reduce 64 partials -> g_M. 32 blocks x 256.
__global__ void k1b() {
    int i = blockIdx.x*256 + threadIdx.x;   // 8192 entries
    float s = 0.f;
    #pragma unroll 8
    for (int oc = 0; oc < NOC; oc++) s += g_Mpart[(size_t)oc*DD*EE + i];
    g_M[i] = s;
}

// Kernel 1c: c[e] = bq . key[e]. 1 block, warp per expert.
__global__ void k1c(const float* __restrict__ bq, const float* __restrict__ key) {
    int w = threadIdx.x >> 5, l = threadIdx.x & 31;
    float s = 0.f;
    for (int o = l; o < DD; o += 32) s = fmaf(bq[o], key[w*DD + o], s);
    #pragma unroll
    for (int off = 16; off; off >>= 1) s += __shfl_down_sync(0xffffffffu, s, off);
    if (l == 0) g_c[w] = s;
}

// launch-index filler so k2 lands on ncu's "-s 5" capture slot
__global__ void k_dummy() {}

// ============================================================
// Kernel 2: cp.async double-buffered streaming. 2 tokens/thread.
// dyn smem = M (32KB) + 2 x-tiles (36KB each) = 106496 B -> 2 blocks/SM
// ============================================================
__global__ void __launch_bounds__(THR2) k2_main(const float* __restrict__ x) {
    extern __shared__ float smem[];
    float* Msh   = smem;                 // DD*EE
    float* tile0 = smem + DD*EE;
    float* tile1 = tile0 + TILE_F;
    const int tid  = threadIdx.x;
    const int tok0 = blockIdx.x * TOKB;
    const unsigned int t0a = (unsigned int)__cvta_generic_to_shared(tile0);
    const unsigned int t1a = (unsigned int)__cvta_generic_to_shared(tile1);

    // preload chunk 0 into tile0
    #pragma unroll
    for (int i = 0; i < 16; i++) {
        int idx = i*THR2 + tid;
        int r = idx >> 3, j4 = idx & 7;
        cpa16(t0a + (unsigned int)(r*ROWP + j4*4)*4u,
              x + (size_t)(tok0 + r)*DD + j4*4);
    }
    asm volatile("cp.async.commit_group;\n" ::: "memory");

    // stage M into shared while chunk 0 is in flight
    #pragma unroll 4
    for (int i = tid; i < DD*EE/4; i += THR2)
        ((float4*)Msh)[i] = ((const float4*)g_M)[i];

    unsigned long long a0=0,a1=0,a2=0,a3=0, b0=0,b1=0,b2=0,b3=0;
    const ulonglong2* M128 = (const ulonglong2*)Msh;

    for (int c = 0; c < NCH; c++) {
        if (c + 1 < NCH) {
            const unsigned int nxt = (c & 1) ? t0a : t1a;
            const int d0n = (c + 1)*CH;
            #pragma unroll
            for (int i = 0; i < 16; i++) {
                int idx = i*THR2 + tid;
                int r = idx >> 3, j4 = idx & 7;
                cpa16(nxt + (unsigned int)(r*ROWP + j4*4)*4u,
                      x + (size_t)(tok0 + r)*DD + d0n + j4*4);
            }
            asm volatile("cp.async.commit_group;\n" ::: "memory");
            asm volatile("cp.async.wait_group 1;\n" ::: "memory");  // chunk c done
        } else {
            asm volatile("cp.async.wait_group 0;\n" ::: "memory");
        }
        __syncthreads();

        const float* tcur = (c & 1) ? tile1 : tile0;
        const float* rowA = tcur + tid*ROWP;
        const float* rowB = rowA + 128*ROWP;
        const int dbase = c*CH;
        #pragma unroll
        for (int j4 = 0; j4 < 8; j4++) {
            float4 xa = *(const float4*)(rowA + j4*4);
            float4 xb = *(const float4*)(rowB + j4*4);
            const int d = dbase + j4*4;
            #pragma unroll
            for (int u = 0; u < 4; u++) {
                ulonglong2 p0 = M128[(d + u)*2];
                ulonglong2 p1 = M128[(d + u)*2 + 1];
                float xs = (u == 0) ? xa.x : (u == 1) ? xa.y : (u == 2) ? xa.z : xa.w;
                float xt = (u == 0) ? xb.x : (u == 1) ? xb.y : (u == 2) ? xb.z : xb.w;
                unsigned long long pa, pb;
                PACKF2(pa, xs, xs);
                PACKF2(pb, xt, xt);
                FFMA2(a0, pa, p0.x); FFMA2(a1, pa, p0.y);
                FFMA2(a2, pa, p1.x); FFMA2(a3, pa, p1.y);
                FFMA2(b0, pb, p0.x); FFMA2(b1, pb, p0.y);
                FFMA2(b2, pb, p1.x); FFMA2(b3, pb, p1.y);
            }
        }
        __syncthreads();
    }

    float la[EE], lb[EE];
    UNPACKF2(la[0], la[1], a0); UNPACKF2(la[2], la[3], a1);
    UNPACKF2(la[4], la[5], a2); UNPACKF2(la[6], la[7], a3);
    UNPACKF2(lb[0], lb[1], b0); UNPACKF2(lb[2], lb[3], b1);
    UNPACKF2(lb[4], lb[5], b2); UNPACKF2(lb[6], lb[7], b3);

    const float scale = 0.03125f;  // 1024^-0.5
    float w[EE], aux = 0.f;
    #pragma unroll
    for (int e = 0; e < EE; e++) w[e] = 0.f;

    #pragma unroll
    for (int t = 0; t < 2; t++) {
        float* lg = t ? lb : la;
        float l[EE];
        #pragma unroll
        for (int e = 0; e < EE; e++) l[e] = (lg[e] + g_c[e]) * scale;
        float m = l[0];
        #pragma unroll
        for (int e = 1; e < EE; e++) m = fmaxf(m, l[e]);
        float wt[EE], sum = 0.f;
        #pragma unroll
        for (int e = 0; e < EE; e++) { wt[e] = expf(l[e] - m); sum += wt[e]; }
        float inv = 1.f / sum;
        #pragma unroll
        for (int e = 0; e < EE; e++) {
            wt[e] *= inv;
            aux += wt[e] * logf(wt[e] + 1e-9f);
            w[e] += wt[e];
        }
    }

    // deterministic block reduction (4 warps)
    #pragma unroll
    for (int e = 0; e < EE; e++) {
        #pragma unroll
        for (int off = 16; off; off >>= 1) w[e] += __shfl_down_sync(0xffffffffu, w[e], off);
    }
    #pragma unroll
    for (int off = 16; off; off >>= 1) aux += __shfl_down_sync(0xffffffffu, aux, off);

    __shared__ float rs[4][9];
    __shared__ float ra[4];
    int wid = tid >> 5, lid = tid & 31;
    if (lid == 0) {
        #pragma unroll
        for (int e = 0; e < EE; e++) rs[wid][e] = w[e];
        ra[wid] = aux;
    }
    __syncthreads();
    if (tid < EE) {
        float s = 0.f;
        #pragma unroll
        for (int k = 0; k < 4; k++) s += rs[k][tid];
        g_part_scores[blockIdx.x*EE + tid] = s;
    }
    if (tid == EE) {
        float s = 0.f;
        #pragma unroll
        for (int k = 0; k < 4; k++) s += ra[k];
        g_part_aux[blockIdx.x] = s;
    }
}

// ============================================================
// Kernel 3: finalize (top-2 with jax tie rule, mask2d, KL + aux -> loss)
// ============================================================
__global__ void k3_finalize(float* __restrict__ out) {
    __shared__ float sc[64][EE];
    __shared__ int cnt[EE];
    __shared__ float ax[256];
    int tid = threadIdx.x;
    if (tid < EE) cnt[tid] = 0;
    ax[tid] = g_part_aux[tid];
    if (tid < BB) {
        #pragma unroll
        for (int e = 0; e < EE; e++) {
            float s = 0.f;
            #pragma unroll
            for (int c = 0; c < 4; c++) s += g_part_scores[(tid*4 + c)*EE + e];
            sc[tid][e] = s;   // proportional to mean; top-k invariant
        }
    }
    __syncthreads();
    if (tid < BB) {
        int i0 = 0; float v0 = sc[tid][0];
        #pragma unroll
        for (int e = 1; e < EE; e++) if (sc[tid][e] > v0) { v0 = sc[tid][e]; i0 = e; }
        int i1 = -1; float v1 = -3.402823466e38f;
        #pragma unroll
        for (int e = 0; e < EE; e++) if (e != i0 && sc[tid][e] > v1) { v1 = sc[tid][e]; i1 = e; }
        out[OFF_IDX + tid*KK + 0] = (float)i0;
        out[OFF_IDX + tid*KK + 1] = (float)i1;
        #pragma unroll
        for (int e = 0; e < EE; e++)
            g_mask2d[tid*EE + e] = (e == i0 || e == i1) ? 1.f : 0.f;
        atomicAdd(&cnt[i0], 1);
        atomicAdd(&cnt[i1], 1);
    }
    __syncthreads();
    for (int s = 128; s > 0; s >>= 1) {
        if (tid < s) ax[tid] += ax[tid + s];
        __syncthreads();
    }
    if (tid == 0) {
        float aux_mean = ax[0] / (float)(BB*SS*EE);
        const float ideal = 1.0f / (float)EE;
        float kl = 0.f;
        #pragma unroll
        for (int e = 0; e < EE; e++) {
            float up = (float)cnt[e] / (float)BB;
            kl += ideal * (logf(ideal) - logf(up));
        }
        kl /= (float)EE;
        out[OFF_LOSS] = 1e-3f * kl + 1e-3f * aux_mean;
    }
}

// ============================================================
// Kernel 4: broadcast mask2d -> mask[B,S,E]
// ============================================================
__global__ void k4_mask(float* __restrict__ out) {
    int t = blockIdx.x * blockDim.x + threadIdx.x;
    if (t >= BB*SS) return;
    int b = t >> 10;
    const float4* mm = (const float4*)&g_mask2d[b*EE];
    float4 m0 = mm[0], m1 = mm[1];
    float4* o = (float4*)(out + (size_t)t*EE);
    o[0] = m0; o[1] = m1;
}

// ============================================================
extern "C" void kernel_launch(void* const* d_in, const int* in_sizes, int n_in,
                              void* d_out, int out_size) {
    const float* x   = (const float*)d_in[0];
    const float* Wq  = (const float*)d_in[1];
    const float* bq  = (const float*)d_in[2];
    const float* key = (const float*)d_in[3];
    float* out = (float*)d_out;

    k1a<<<128, 256>>>(Wq, key, 0);          // launch 0
    k1a<<<128, 256>>>(Wq, key, 1);          // launch 1
    k1b<<<32, 256>>>();                     // launch 2
    k1c<<<1, 256>>>(bq, key);               // launch 3
    k_dummy<<<1, 32>>>();                   // launch 4

    size_t sm2 = (size_t)(DD*EE + 2*TILE_F) * sizeof(float);  // 106496 B
    cudaFuncSetAttribute(k2_main, cudaFuncAttributeMaxDynamicSharedMemorySize, (int)sm2);
    k2_main<<<NBLK2, THR2, sm2>>>(x);       // launch 5  <- ncu -s 5 captures this

    k3_finalize<<<1, 256>>>(out);           // launch 6
    k4_mask<<<(BB*SS + 255)/256, 256>>>(out);  // launch 7
}

// round 7
// speedup vs baseline: 4.7742x; 1.1499x over previous
#include <cuda_runtime.h>
#include <cstdint>
#include <math.h>

// Problem constants
#define BB   64
#define SS   1024
#define DD   1024
#define EE   8
#define KK   2

// k2 config
#define THR2  128             // threads per block
#define TOKB  256             // tokens per block (2 per thread: tid, tid+128)
#define NBLK2 (BB*SS/TOKB)    // 256 blocks
#define CH    32              // d-chunk per pipeline stage
#define NCH   (DD/CH)         // 32 stages
#define ROWP  36              // padded row (floats): 4-bank lane stride -> conflict-free LDS.128
#define TILE_F (TOKB*ROWP)    // 9216 floats per tile buffer

// k1 config
#define OCHUNK 16
#define NOC    64             // o-chunks

#define OFF_IDX  (BB*SS*EE)          // 524288
#define OFF_LOSS (OFF_IDX + BB*KK)   // 524416

// ---------------- scratch (no allocations allowed) ----------------
__device__ __align__(16) float g_Mpart[NOC*DD*EE];   // 2 MB split-K partials
__device__ __align__(16) float g_M[DD*EE];           // folded weight M[d][e]
__device__ __align__(16) float g_c[EE];              // folded bias c[e]
__device__ __align__(16) float g_part_scores[NBLK2*EE];
__device__ __align__(16) float g_part_aux[NBLK2];

// ---------------- packed f32x2 helpers (Blackwell FFMA2) ----------------
#define PACKF2(dst, lo, hi) asm("mov.b64 %0, {%1, %2};" : "=l"(dst) : "f"(lo), "f"(hi))
#define UNPACKF2(lo, hi, src) asm("mov.b64 {%0, %1}, %2;" : "=f"(lo), "=f"(hi) : "l"(src))
#define FFMA2(acc, a, b) asm("fma.rn.f32x2 %0, %1, %2, %0;" : "+l"(acc) : "l"(a), "l"(b))

__device__ __forceinline__ void cpa16(unsigned int sdst, const float* gsrc) {
    asm volatile("cp.async.cg.shared.global [%0], [%1], 16;\n" :: "r"(sdst), "l"(gsrc));
}

// ============================================================
// Kernel 1a: split-K partials of M[d][e] = sum_o Wq[o][d]*key[e][o]
// grid = 256 blocks x 256 thr. block -> (o-chunk of 16, d-quarter of 256).
// ============================================================
__global__ void k1a(const float* __restrict__ Wq, const float* __restrict__ key) {
    __shared__ float ks[OCHUNK][EE];
    const int tid = threadIdx.x;
    const int oc = blockIdx.x >> 2;        // 0..63
    const int q  = blockIdx.x & 3;
    if (tid < OCHUNK*EE) {
        int ol = tid >> 3, e = tid & 7;
        ks[ol][e] = key[e*DD + oc*OCHUNK + ol];
    }
    __syncthreads();
    const int d = q*256 + tid;
    const int o0 = oc*OCHUNK;
    float acc[EE];
    #pragma unroll
    for (int e = 0; e < EE; e++) acc[e] = 0.f;
    #pragma unroll
    for (int j = 0; j < OCHUNK; j++) {
        float w = Wq[(size_t)(o0 + j)*DD + d];     // coalesced, MLP=16
        #pragma unroll
        for (int e = 0; e < EE; e++) acc[e] = fmaf(w, ks[j][e], acc[e]);
    }
    float4* dst = (float4*)&g_Mpart[(size_t)oc*DD*EE + (size_t)d*EE];
    dst[0] = make_float4(acc[0], acc[1], acc[2], acc[3]);
    dst[1] = make_float4(acc[4], acc[5], acc[6], acc[7]);
}

// ============================================================
// Kernel 1b: blocks 0..31 reduce 64 partials -> g_M;
//            block 32 computes c[e] = bq . key[e] (warp per expert).
// ============================================================
__global__ void k1b(const float* __restrict__ bq, const float* __restrict__ key) {
    if (blockIdx.x < 32) {
        int i = blockIdx.x*256 + threadIdx.x;   // 8192 entries
        float s = 0.f;
        #pragma unroll 8
        for (int oc = 0; oc < NOC; oc++) s += g_Mpart[(size_t)oc*DD*EE + i];
        g_M[i] = s;
    } else {
        int w = threadIdx.x >> 5, l = threadIdx.x & 31;
        float s = 0.f;
        #pragma unroll 8
        for (int o = l; o < DD; o += 32) s = fmaf(bq[o], key[w*DD + o], s);
        #pragma unroll
        for (int off = 16; off; off >>= 1) s += __shfl_down_sync(0xffffffffu, s, off);
        if (l == 0) g_c[w] = s;
    }
}

// ============================================================
// Kernel 2: cp.async double-buffered streaming. 2 tokens/thread.
// dyn smem = M (32KB) + 2 x-tiles (36KB each) = 106496 B -> 2 blocks/SM
// ============================================================
__global__ void __launch_bounds__(THR2) k2_main(const float* __restrict__ x) {
    extern __shared__ float smem[];
    float* Msh   = smem;                 // DD*EE
    float* tile0 = smem + DD*EE;
    float* tile1 = tile0 + TILE_F;
    const int tid  = threadIdx.x;
    const int tok0 = blockIdx.x * TOKB;
    const unsigned int t0a = (unsigned int)__cvta_generic_to_shared(tile0);
    const unsigned int t1a = (unsigned int)__cvta_generic_to_shared(tile1);

    // preload chunk 0 into tile0
    #pragma unroll
    for (int i = 0; i < 16; i++) {
        int idx = i*THR2 + tid;
        int r = idx >> 3, j4 = idx & 7;
        cpa16(t0a + (unsigned int)(r*ROWP + j4*4)*4u,
              x + (size_t)(tok0 + r)*DD + j4*4);
    }
    asm volatile("cp.async.commit_group;\n" ::: "memory");

    // stage M into shared while chunk 0 is in flight
    #pragma unroll 4
    for (int i = tid; i < DD*EE/4; i += THR2)
        ((float4*)Msh)[i] = ((const float4*)g_M)[i];

    unsigned long long a0=0,a1=0,a2=0,a3=0, b0=0,b1=0,b2=0,b3=0;
    const ulonglong2* M128 = (const ulonglong2*)Msh;

    for (int c = 0; c < NCH; c++) {
        if (c + 1 < NCH) {
            const unsigned int nxt = (c & 1) ? t0a : t1a;
            const int d0n = (c + 1)*CH;
            #pragma unroll
            for (int i = 0; i < 16; i++) {
                int idx = i*THR2 + tid;
                int r = idx >> 3, j4 = idx & 7;
                cpa16(nxt + (unsigned int)(r*ROWP + j4*4)*4u,
                      x + (size_t)(tok0 + r)*DD + d0n + j4*4);
            }
            asm volatile("cp.async.commit_group;\n" ::: "memory");
            asm volatile("cp.async.wait_group 1;\n" ::: "memory");  // chunk c done
        } else {
            asm volatile("cp.async.wait_group 0;\n" ::: "memory");
        }
        __syncthreads();

        const float* tcur = (c & 1) ? tile1 : tile0;
        const float* rowA = tcur + tid*ROWP;
        const float* rowB = rowA + 128*ROWP;
        const int dbase = c*CH;
        #pragma unroll
        for (int j4 = 0; j4 < 8; j4++) {
            float4 xa = *(const float4*)(rowA + j4*4);
            float4 xb = *(const float4*)(rowB + j4*4);
            const int d = dbase + j4*4;
            #pragma unroll
            for (int u = 0; u < 4; u++) {
                ulonglong2 p0 = M128[(d + u)*2];
                ulonglong2 p1 = M128[(d + u)*2 + 1];
                float xs = (u == 0) ? xa.x : (u == 1) ? xa.y : (u == 2) ? xa.z : xa.w;
                float xt = (u == 0) ? xb.x : (u == 1) ? xb.y : (u == 2) ? xb.z : xb.w;
                unsigned long long pa, pb;
                PACKF2(pa, xs, xs);
                PACKF2(pb, xt, xt);
                FFMA2(a0, pa, p0.x); FFMA2(a1, pa, p0.y);
                FFMA2(a2, pa, p1.x); FFMA2(a3, pa, p1.y);
                FFMA2(b0, pb, p0.x); FFMA2(b1, pb, p0.y);
                FFMA2(b2, pb, p1.x); FFMA2(b3, pb, p1.y);
            }
        }
        __syncthreads();
    }

    float la[EE], lb[EE];
    UNPACKF2(la[0], la[1], a0); UNPACKF2(la[2], la[3], a1);
    UNPACKF2(la[4], la[5], a2); UNPACKF2(la[6], la[7], a3);
    UNPACKF2(lb[0], lb[1], b0); UNPACKF2(lb[2], lb[3], b1);
    UNPACKF2(lb[4], lb[5], b2); UNPACKF2(lb[6], lb[7], b3);

    const float scale = 0.03125f;  // 1024^-0.5
    float w[EE], aux = 0.f;
    #pragma unroll
    for (int e = 0; e < EE; e++) w[e] = 0.f;

    #pragma unroll
    for (int t = 0; t < 2; t++) {
        float* lg = t ? lb : la;
        float l[EE];
        #pragma unroll
        for (int e = 0; e < EE; e++) l[e] = (lg[e] + g_c[e]) * scale;
        float m = l[0];
        #pragma unroll
        for (int e = 1; e < EE; e++) m = fmaxf(m, l[e]);
        float wt[EE], sum = 0.f;
        #pragma unroll
        for (int e = 0; e < EE; e++) { wt[e] = expf(l[e] - m); sum += wt[e]; }
        float inv = 1.f / sum;
        #pragma unroll
        for (int e = 0; e < EE; e++) {
            wt[e] *= inv;
            aux += wt[e] * logf(wt[e] + 1e-9f);
            w[e] += wt[e];
        }
    }

    // deterministic block reduction (4 warps)
    #pragma unroll
    for (int e = 0; e < EE; e++) {
        #pragma unroll
        for (int off = 16; off; off >>= 1) w[e] += __shfl_down_sync(0xffffffffu, w[e], off);
    }
    #pragma unroll
    for (int off = 16; off; off >>= 1) aux += __shfl_down_sync(0xffffffffu, aux, off);

    __shared__ float rs[4][9];
    __shared__ float ra[4];
    int wid = tid >> 5, lid = tid & 31;
    if (lid == 0) {
        #pragma unroll
        for (int e = 0; e < EE; e++) rs[wid][e] = w[e];
        ra[wid] = aux;
    }
    __syncthreads();
    if (tid < EE) {
        float s = 0.f;
        #pragma unroll
        for (int k = 0; k < 4; k++) s += rs[k][tid];
        g_part_scores[blockIdx.x*EE + tid] = s;
    }
    if (tid == EE) {
        float s = 0.f;
        #pragma unroll
        for (int k = 0; k < 4; k++) s += ra[k];
        g_part_aux[blockIdx.x] = s;
    }
}

// ============================================================
// top-2 from 8 scores: jax tie rule (strict > keeps lowest index)
// ============================================================
__device__ __forceinline__ void top2(const float* sc, int& i0, int& i1) {
    i0 = 0; float v0 = sc[0];
    #pragma unroll
    for (int e = 1; e < EE; e++) if (sc[e] > v0) { v0 = sc[e]; i0 = e; }
    i1 = -1; float v1 = -3.402823466e38f;
    #pragma unroll
    for (int e = 0; e < EE; e++) if (e != i0 && sc[e] > v1) { v1 = sc[e]; i1 = e; }
}

// per-batch score sums from k2 partials (deterministic order, identical
// in mask blocks and finalize block)
__device__ __forceinline__ void batch_scores(int b, float* sc) {
    #pragma unroll
    for (int e = 0; e < EE; e++) {
        float s = 0.f;
        #pragma unroll
        for (int c = 0; c < 4; c++) s += g_part_scores[(b*4 + c)*EE + e];
        sc[e] = s;   // proportional to mean; top-k invariant
    }
}

// ============================================================
// Kernel 34: blocks 0..255 write mask for 256 tokens each (recompute
// their batch's top-2 from partials); block 256 writes indices + loss.
// ============================================================
__global__ void k34(float* __restrict__ out) {
    const int tid = threadIdx.x;
    if (blockIdx.x < 256) {
        const int b = blockIdx.x >> 2;          // batch
        float sc[EE];
        batch_scores(b, sc);
        int i0, i1;
        top2(sc, i0, i1);
        float m[EE];
        #pragma unroll
        for (int e = 0; e < EE; e++) m[e] = (e == i0 || e == i1) ? 1.f : 0.f;
        const int t = blockIdx.x*256 + tid;     // token id
        float4* o = (float4*)(out + (size_t)t*EE);
        o[0] = make_float4(m[0], m[1], m[2], m[3]);
        o[1] = make_float4(m[4], m[5], m[6], m[7]);
    } else {
        __shared__ int cnt[EE];
        __shared__ float ax[256];
        if (tid < EE) cnt[tid] = 0;
        ax[tid] = g_part_aux[tid];
        __syncthreads();
        if (tid < BB) {
            float sc[EE];
            batch_scores(tid, sc);
            int i0, i1;
            top2(sc, i0, i1);
            out[OFF_IDX + tid*KK + 0] = (float)i0;
            out[OFF_IDX + tid*KK + 1] = (float)i1;
            atomicAdd(&cnt[i0], 1);
            atomicAdd(&cnt[i1], 1);
        }
        __syncthreads();
        for (int s = 128; s > 0; s >>= 1) {
            if (tid < s) ax[tid] += ax[tid + s];
            __syncthreads();
        }
        if (tid == 0) {
            float aux_mean = ax[0] / (float)(BB*SS*EE);
            const float ideal = 1.0f / (float)EE;
            float kl = 0.f;
            #pragma unroll
            for (int e = 0; e < EE; e++) {
                float up = (float)cnt[e] / (float)BB;
                kl += ideal * (logf(ideal) - logf(up));
            }
            kl /= (float)EE;
            out[OFF_LOSS] = 1e-3f * kl + 1e-3f * aux_mean;
        }
    }
}

// ============================================================
extern "C" void kernel_launch(void* const* d_in, const int* in_sizes, int n_in,
                              void* d_out, int out_size) {
    const float* x   = (const float*)d_in[0];
    const float* Wq  = (const float*)d_in[1];
    const float* bq  = (const float*)d_in[2];
    const float* key = (const float*)d_in[3];
    float* out = (float*)d_out;

    k1a<<<256, 256>>>(Wq, key);             // launch 0
    k1b<<<33, 256>>>(bq, key);              // launch 1

    size_t sm2 = (size_t)(DD*EE + 2*TILE_F) * sizeof(float);  // 106496 B
    cudaFuncSetAttribute(k2_main, cudaFuncAttributeMaxDynamicSharedMemorySize, (int)sm2);
    k2_main<<<NBLK2, THR2, sm2>>>(x);       // launch 2

    k34<<<257, 256>>>(out);                 // launch 3
}